// round 3
// baseline (speedup 1.0000x reference)
#include <cuda_runtime.h>
#include <cstdint>

// SGNS loss, 8 lanes per pair (4 pairs per warp), occupancy-tuned.
// uint32 byte offsets (V*512B < 4GB) + single base pointer; compiler-scheduled
// load batching across the fully unrolled 6-row loop; regs capped at 51 via
// __launch_bounds__(256, 5) -> 5 blocks/SM (40 warps).

#define D 128
#define KNEG 5
#define LPP 8          // lanes per pair
#define VPL 4          // float4 vectors per lane (D/4/LPP)

__device__ __forceinline__ float log_sigmoid(float x) {
    // stable: min(x,0) - log1p(exp(-|x|))
    return fminf(x, 0.0f) - log1pf(__expf(-fabsf(x)));
}

__global__ void __launch_bounds__(256, 5) sgns_loss_kernel(
    const float* __restrict__ emb,
    const float* __restrict__ out_w,
    const int*   __restrict__ tgt_ids,
    const int*   __restrict__ ctx_ids,
    const int*   __restrict__ neg_ids,
    float*       __restrict__ out,
    int N)
{
    const int tid  = blockIdx.x * blockDim.x + threadIdx.x;
    const int pair = tid >> 3;               // 8 lanes per pair
    const int lane = threadIdx.x & (LPP - 1);
    if (pair >= N) return;

    // indices -> uint32 byte offsets into the tables (rows are 512B)
    const unsigned t_off = (unsigned)__ldg(tgt_ids + pair) << 9;
    unsigned roff[1 + KNEG];
    roff[0] = (unsigned)__ldg(ctx_ids + pair) << 9;
#pragma unroll
    for (int k = 0; k < KNEG; k++)
        roff[1 + k] = (unsigned)__ldg(neg_ids + (size_t)pair * KNEG + k) << 9;

    const char* emb_b = reinterpret_cast<const char*>(emb);
    const char* w_b   = reinterpret_cast<const char*>(out_w);
    const unsigned lane_b = (unsigned)lane * 16u;   // float4 within the 128B line

    // input row: lane holds float4 slots {lane, lane+8, lane+16, lane+24}
    float4 iv[VPL];
#pragma unroll
    for (int i = 0; i < VPL; i++)
        iv[i] = __ldg(reinterpret_cast<const float4*>(emb_b + t_off + lane_b + 128u * i));

    float s[1 + KNEG];
#pragma unroll
    for (int j = 0; j < 1 + KNEG; j++) {
        float4 rv[VPL];
#pragma unroll
        for (int i = 0; i < VPL; i++)
            rv[i] = __ldg(reinterpret_cast<const float4*>(w_b + roff[j] + lane_b + 128u * i));
        float acc = 0.f;
#pragma unroll
        for (int i = 0; i < VPL; i++) {
            acc = fmaf(iv[i].x, rv[i].x, acc);
            acc = fmaf(iv[i].y, rv[i].y, acc);
            acc = fmaf(iv[i].z, rv[i].z, acc);
            acc = fmaf(iv[i].w, rv[i].w, acc);
        }
        s[j] = acc;
    }

    // 3-stage butterfly within 8-lane groups; one instruction serves 4 pairs
#pragma unroll
    for (int j = 0; j < 1 + KNEG; j++) {
#pragma unroll
        for (int off = LPP / 2; off > 0; off >>= 1)
            s[j] += __shfl_xor_sync(0xFFFFFFFFu, s[j], off);
    }

    if (lane == 0) {
        float loss = -log_sigmoid(s[0]);
#pragma unroll
        for (int k = 0; k < KNEG; k++)
            loss -= log_sigmoid(-s[1 + k]);
        out[pair] = loss;
    }
}

extern "C" void kernel_launch(void* const* d_in, const int* in_sizes, int n_in,
                              void* d_out, int out_size) {
    const float* emb     = (const float*)d_in[0];
    const float* out_w   = (const float*)d_in[1];
    const int*   tgt_ids = (const int*)d_in[2];
    const int*   ctx_ids = (const int*)d_in[3];
    const int*   neg_ids = (const int*)d_in[4];
    float*       out     = (float*)d_out;

    const int N = in_sizes[2];
    const int threads = 256;                  // 32 pairs per block
    const int pairs_per_block = threads / LPP;
    const int blocks = (N + pairs_per_block - 1) / pairs_per_block;
    sgns_loss_kernel<<<blocks, threads>>>(emb, out_w, tgt_ids, ctx_ids, neg_ids, out, N);
}

// round 4
// speedup vs baseline: 1.0517x; 1.0517x over previous
#include <cuda_runtime.h>
#include <cstdint>

// SGNS loss, 8 lanes per pair (4 pairs per warp). Bandwidth-floor tuned:
//  - R2-style explicit double-buffered row pipeline (best measured schedule)
//  - lane-distributed index fetch (3 predicated LDGs + 7 shfl broadcasts
//    instead of 7 LDGs per group)
//  - __stwt output store (don't evict L2-resident table lines)

#define D 128
#define KNEG 5
#define LPP 8          // lanes per pair
#define VPL 4          // float4 vectors per lane

__device__ __forceinline__ float log_sigmoid(float x) {
    return fminf(x, 0.0f) - log1pf(__expf(-fabsf(x)));
}

__global__ void __launch_bounds__(256) sgns_loss_kernel(
    const float* __restrict__ emb,
    const float* __restrict__ out_w,
    const int*   __restrict__ tgt_ids,
    const int*   __restrict__ ctx_ids,
    const int*   __restrict__ neg_ids,
    float*       __restrict__ out,
    int N)
{
    const int tid  = blockIdx.x * blockDim.x + threadIdx.x;
    const int pair = tid >> 3;
    const int lane = threadIdx.x & (LPP - 1);
    if (pair >= N) return;

    // mask naming only this 8-lane group (whole group shares `pair`, so the
    // group exits together and the shuffles are safe even with a ragged tail)
    const unsigned gmask = 0xFFu << ((threadIdx.x & 31) & ~(LPP - 1));

    // Distributed index fetch: slot 0=tgt, 1=ctx, 2..6=neg[0..4]
    int myidx = 0;
    if (lane == 0)      myidx = __ldg(tgt_ids + pair);
    else if (lane == 1) myidx = __ldg(ctx_ids + pair);
    else if (lane < 7)  myidx = __ldg(neg_ids + pair * KNEG + (lane - 2));

    const unsigned t_off = (unsigned)__shfl_sync(gmask, myidx, 0, LPP) << 9;
    unsigned roff[1 + KNEG];
#pragma unroll
    for (int j = 0; j < 1 + KNEG; j++)
        roff[j] = (unsigned)__shfl_sync(gmask, myidx, 1 + j, LPP) << 9;

    const char* emb_b = reinterpret_cast<const char*>(emb);
    const char* w_b   = reinterpret_cast<const char*>(out_w);
    const unsigned lane_b = (unsigned)lane * 16u;

    // input row: lane holds float4 slots {lane, lane+8, lane+16, lane+24}
    float4 iv[VPL];
#pragma unroll
    for (int i = 0; i < VPL; i++)
        iv[i] = __ldg(reinterpret_cast<const float4*>(emb_b + t_off + lane_b + 128u * i));

    // double-buffered walk over the 6 out_w rows
    float4 cur[VPL], nxt[VPL];
#pragma unroll
    for (int i = 0; i < VPL; i++)
        cur[i] = __ldg(reinterpret_cast<const float4*>(w_b + roff[0] + lane_b + 128u * i));

    float s[1 + KNEG];
#pragma unroll
    for (int j = 0; j < 1 + KNEG; j++) {
        if (j < KNEG) {
#pragma unroll
            for (int i = 0; i < VPL; i++)
                nxt[i] = __ldg(reinterpret_cast<const float4*>(w_b + roff[j + 1] + lane_b + 128u * i));
        }
        float acc = 0.f;
#pragma unroll
        for (int i = 0; i < VPL; i++) {
            acc = fmaf(iv[i].x, cur[i].x, acc);
            acc = fmaf(iv[i].y, cur[i].y, acc);
            acc = fmaf(iv[i].z, cur[i].z, acc);
            acc = fmaf(iv[i].w, cur[i].w, acc);
        }
        s[j] = acc;
        if (j < KNEG) {
#pragma unroll
            for (int i = 0; i < VPL; i++)
                cur[i] = nxt[i];
        }
    }

    // 3-stage butterfly within 8-lane groups (one instruction serves 4 pairs)
#pragma unroll
    for (int j = 0; j < 1 + KNEG; j++) {
#pragma unroll
        for (int off = LPP / 2; off > 0; off >>= 1)
            s[j] += __shfl_xor_sync(gmask, s[j], off, LPP);
    }

    if (lane == 0) {
        float loss = -log_sigmoid(s[0]);
#pragma unroll
        for (int k = 0; k < KNEG; k++)
            loss -= log_sigmoid(-s[1 + k]);
        __stwt(out + pair, loss);   // streaming store: keep L2 for the tables
    }
}

extern "C" void kernel_launch(void* const* d_in, const int* in_sizes, int n_in,
                              void* d_out, int out_size) {
    const float* emb     = (const float*)d_in[0];
    const float* out_w   = (const float*)d_in[1];
    const int*   tgt_ids = (const int*)d_in[2];
    const int*   ctx_ids = (const int*)d_in[3];
    const int*   neg_ids = (const int*)d_in[4];
    float*       out     = (float*)d_out;

    const int N = in_sizes[2];
    const int threads = 256;                  // 32 pairs per block
    const int pairs_per_block = threads / LPP;
    const int blocks = (N + pairs_per_block - 1) / pairs_per_block;
    sgns_loss_kernel<<<blocks, threads>>>(emb, out_w, tgt_ids, ctx_ids, neg_ids, out, N);
}

// round 5
// speedup vs baseline: 1.0852x; 1.0319x over previous
#include <cuda_runtime.h>
#include <cstdint>

// SGNS loss, 8 lanes per pair (4 pairs per warp), L2-policy tuned:
//  - out_w rows (6/7 of traffic, ~16x L2 reuse) loaded with L2::evict_last
//  - emb rows (1/7 of traffic, ~2.6x reuse) loaded with L2::evict_first
//  - __stwt output store (no L2 write-allocate pollution)
//  - R2-style double-buffered row pipeline, distributed index fetch

#define D 128
#define KNEG 5
#define LPP 8          // lanes per pair
#define VPL 4          // float4 vectors per lane

__device__ __forceinline__ float log_sigmoid(float x) {
    return fminf(x, 0.0f) - log1pf(__expf(-fabsf(x)));
}

__device__ __forceinline__ float4 ldg_hint(const void* p, uint64_t pol) {
    float4 v;
    asm volatile("ld.global.nc.L2::cache_hint.v4.f32 {%0,%1,%2,%3}, [%4], %5;"
                 : "=f"(v.x), "=f"(v.y), "=f"(v.z), "=f"(v.w)
                 : "l"(p), "l"(pol));
    return v;
}

__global__ void __launch_bounds__(256) sgns_loss_kernel(
    const float* __restrict__ emb,
    const float* __restrict__ out_w,
    const int*   __restrict__ tgt_ids,
    const int*   __restrict__ ctx_ids,
    const int*   __restrict__ neg_ids,
    float*       __restrict__ out,
    int N)
{
    const int tid  = blockIdx.x * blockDim.x + threadIdx.x;
    const int pair = tid >> 3;
    const int lane = threadIdx.x & (LPP - 1);
    if (pair >= N) return;

    // L2 eviction policies
    uint64_t pol_last, pol_first;
    asm("createpolicy.fractional.L2::evict_last.b64 %0, 1.0;"  : "=l"(pol_last));
    asm("createpolicy.fractional.L2::evict_first.b64 %0, 1.0;" : "=l"(pol_first));

    // mask naming only this 8-lane group
    const unsigned gmask = 0xFFu << ((threadIdx.x & 31) & ~(LPP - 1));

    // Distributed index fetch: slot 0=tgt, 1=ctx, 2..6=neg[0..4]
    int myidx = 0;
    if (lane == 0)      myidx = __ldg(tgt_ids + pair);
    else if (lane == 1) myidx = __ldg(ctx_ids + pair);
    else if (lane < 7)  myidx = __ldg(neg_ids + pair * KNEG + (lane - 2));

    const unsigned t_off = (unsigned)__shfl_sync(gmask, myidx, 0, LPP) << 9;
    unsigned roff[1 + KNEG];
#pragma unroll
    for (int j = 0; j < 1 + KNEG; j++)
        roff[j] = (unsigned)__shfl_sync(gmask, myidx, 1 + j, LPP) << 9;

    const char* emb_b = reinterpret_cast<const char*>(emb);
    const char* w_b   = reinterpret_cast<const char*>(out_w);
    const unsigned lane_b = (unsigned)lane * 16u;

    // input row (evict_first: low reuse, don't displace out_w)
    float4 iv[VPL];
#pragma unroll
    for (int i = 0; i < VPL; i++)
        iv[i] = ldg_hint(emb_b + t_off + lane_b + 128u * i, pol_first);

    // double-buffered walk over the 6 out_w rows (evict_last: keep resident)
    float4 cur[VPL], nxt[VPL];
#pragma unroll
    for (int i = 0; i < VPL; i++)
        cur[i] = ldg_hint(w_b + roff[0] + lane_b + 128u * i, pol_last);

    float s[1 + KNEG];
#pragma unroll
    for (int j = 0; j < 1 + KNEG; j++) {
        if (j < KNEG) {
#pragma unroll
            for (int i = 0; i < VPL; i++)
                nxt[i] = ldg_hint(w_b + roff[j + 1] + lane_b + 128u * i, pol_last);
        }
        float acc = 0.f;
#pragma unroll
        for (int i = 0; i < VPL; i++) {
            acc = fmaf(iv[i].x, cur[i].x, acc);
            acc = fmaf(iv[i].y, cur[i].y, acc);
            acc = fmaf(iv[i].z, cur[i].z, acc);
            acc = fmaf(iv[i].w, cur[i].w, acc);
        }
        s[j] = acc;
        if (j < KNEG) {
#pragma unroll
            for (int i = 0; i < VPL; i++)
                cur[i] = nxt[i];
        }
    }

    // 3-stage butterfly within 8-lane groups (one instruction serves 4 pairs)
#pragma unroll
    for (int j = 0; j < 1 + KNEG; j++) {
#pragma unroll
        for (int off = LPP / 2; off > 0; off >>= 1)
            s[j] += __shfl_xor_sync(gmask, s[j], off, LPP);
    }

    if (lane == 0) {
        float loss = -log_sigmoid(s[0]);
#pragma unroll
        for (int k = 0; k < KNEG; k++)
            loss -= log_sigmoid(-s[1 + k]);
        __stwt(out + pair, loss);
    }
}

extern "C" void kernel_launch(void* const* d_in, const int* in_sizes, int n_in,
                              void* d_out, int out_size) {
    const float* emb     = (const float*)d_in[0];
    const float* out_w   = (const float*)d_in[1];
    const int*   tgt_ids = (const int*)d_in[2];
    const int*   ctx_ids = (const int*)d_in[3];
    const int*   neg_ids = (const int*)d_in[4];
    float*       out     = (float*)d_out;

    const int N = in_sizes[2];
    const int threads = 256;                  // 32 pairs per block
    const int pairs_per_block = threads / LPP;
    const int blocks = (N + pairs_per_block - 1) / pairs_per_block;
    sgns_loss_kernel<<<blocks, threads>>>(emb, out_w, tgt_ids, ctx_ids, neg_ids, out, N);
}